// round 4
// baseline (speedup 1.0000x reference)
#include <cuda_runtime.h>
#include <math.h>

// Problem constants
#define PB 2
#define PS 2048
#define PE 1024
#define PH 16
#define PD 64
// 3E = 3072

// Scratch (allocation-free rule: __device__ globals)
__device__ float g_qkv[PB * PS * 3 * PE];   // [B*S, 3E] row-major
__device__ float g_attn[PB * PS * PE];      // [B*S, E]  row-major

// ---------------------------------------------------------------------------
// NT GEMM: C[M,N] = A[M,K] * B[N,K]^T + bias[N]
// A, B row-major (K contiguous). 128x128x16 tiles, 256 threads, 8x8 microtile.
// ---------------------------------------------------------------------------
__global__ __launch_bounds__(256, 2) void gemm_nt_bias(
    const float* __restrict__ A, const float* __restrict__ Bm,
    const float* __restrict__ bias, float* __restrict__ C,
    int M, int N, int K)
{
    __shared__ __align__(16) float As[16][132];
    __shared__ __align__(16) float Bs[16][132];

    const int tid = threadIdx.x;
    const int ty = tid >> 4;         // 0..15 (row group)
    const int tx = tid & 15;         // 0..15 (col group)
    const int m0 = blockIdx.y * 128;
    const int n0 = blockIdx.x * 128;
    const int lr = tid >> 2;         // 0..63  load row
    const int lc = (tid & 3) << 2;   // 0,4,8,12 load col (float4)

    float acc[8][8];
#pragma unroll
    for (int i = 0; i < 8; ++i)
#pragma unroll
        for (int j = 0; j < 8; ++j) acc[i][j] = 0.f;

    const float* Ap = A + (size_t)m0 * K;
    const float* Bp = Bm + (size_t)n0 * K;

    for (int k0 = 0; k0 < K; k0 += 16) {
#pragma unroll
        for (int p = 0; p < 2; ++p) {
            const int r = lr + p * 64;
            float4 av = *(const float4*)(Ap + (size_t)r * K + k0 + lc);
            As[lc + 0][r] = av.x; As[lc + 1][r] = av.y;
            As[lc + 2][r] = av.z; As[lc + 3][r] = av.w;
            float4 bv = *(const float4*)(Bp + (size_t)r * K + k0 + lc);
            Bs[lc + 0][r] = bv.x; Bs[lc + 1][r] = bv.y;
            Bs[lc + 2][r] = bv.z; Bs[lc + 3][r] = bv.w;
        }
        __syncthreads();

#pragma unroll
        for (int k = 0; k < 16; ++k) {
            float4 a0 = *(const float4*)&As[k][ty * 8];
            float4 a1 = *(const float4*)&As[k][ty * 8 + 4];
            float4 b0 = *(const float4*)&Bs[k][tx * 8];
            float4 b1 = *(const float4*)&Bs[k][tx * 8 + 4];
            float a[8] = {a0.x, a0.y, a0.z, a0.w, a1.x, a1.y, a1.z, a1.w};
            float bb[8] = {b0.x, b0.y, b0.z, b0.w, b1.x, b1.y, b1.z, b1.w};
#pragma unroll
            for (int i = 0; i < 8; ++i)
#pragma unroll
                for (int j = 0; j < 8; ++j)
                    acc[i][j] += a[i] * bb[j];
        }
        __syncthreads();
    }

#pragma unroll
    for (int i = 0; i < 8; ++i) {
        const size_t row = (size_t)(m0 + ty * 8 + i);
        float* Cp = C + row * N + n0 + tx * 8;
        const float* bp = bias + n0 + tx * 8;
        float4 o0 = {acc[i][0] + bp[0], acc[i][1] + bp[1],
                     acc[i][2] + bp[2], acc[i][3] + bp[3]};
        float4 o1 = {acc[i][4] + bp[4], acc[i][5] + bp[5],
                     acc[i][6] + bp[6], acc[i][7] + bp[7]};
        *(float4*)(Cp + 0) = o0;
        *(float4*)(Cp + 4) = o1;
    }
}

// ---------------------------------------------------------------------------
// Flash attention with multiplicative exponential distance decay.
// Per CTA: 128 query rows of one (b, h); loop over 32 key tiles of 64.
// Thread layout 16x16: each thread owns 8 q-rows (ty*8+i) x 4 cols (tx*4+j).
// Smem (dynamic, 102400 B):
//   Qs [d=64][r=128] stride 132 (d-major, pre-scaled by 1/8)
//   Ks [d=64][t=64]  stride 68  (d-major)
//   Vs [t=64][d=64]  stride 68  (t-major rows)
//   Ps [t=64][r=128] stride 132 (t-major)
// ---------------------------------------------------------------------------
__global__ __launch_bounds__(256, 2) void attn_kernel(
    const float* __restrict__ qkv, float* __restrict__ outp,
    const float* __restrict__ dd)
{
    extern __shared__ float sm[];
    float* Qs = sm;               // 64*132 = 8448 floats
    float* Ks = sm + 8448;        // 64*68  = 4352
    float* Vs = sm + 12800;       // 64*68  = 4352
    float* Ps = sm + 17152;       // 64*132 = 8448  (total 25600 floats)

    const int tid = threadIdx.x;
    const int ty = tid >> 4;
    const int tx = tid & 15;
    const int bh = blockIdx.y;
    const int b = bh >> 4;
    const int h = bh & 15;
    const int q0 = blockIdx.x * 128;
    const float absA = fabsf(dd[0]);

    const size_t qkv_b = (size_t)b * PS * 3072;
    const int c0 = tx << 2;       // 0..60 (head-dim float4 slot)
    const int rb = ty;            // load row base

    // Load + scale Q tile (transpose to d-major)
#pragma unroll
    for (int p = 0; p < 8; ++p) {
        const int r = rb + p * 16;
        float4 v = *(const float4*)(qkv + qkv_b + (size_t)(q0 + r) * 3072 + h * 64 + c0);
        Qs[(c0 + 0) * 132 + r] = v.x * 0.125f;
        Qs[(c0 + 1) * 132 + r] = v.y * 0.125f;
        Qs[(c0 + 2) * 132 + r] = v.z * 0.125f;
        Qs[(c0 + 3) * 132 + r] = v.w * 0.125f;
    }

    float m_i[8], l_i[8], o[8][4];
#pragma unroll
    for (int i = 0; i < 8; ++i) {
        m_i[i] = -INFINITY; l_i[i] = 0.f;
        o[i][0] = o[i][1] = o[i][2] = o[i][3] = 0.f;
    }

    for (int kt = 0; kt < 32; ++kt) {
        __syncthreads();  // prior PV done; Qs visible on first iter
        // Load K (transpose to d-major) and V (row-major) for this tile
#pragma unroll
        for (int p = 0; p < 4; ++p) {
            const int t = rb + p * 16;
            const size_t g = qkv_b + (size_t)(kt * 64 + t) * 3072 + h * 64 + c0;
            float4 kv = *(const float4*)(qkv + g + 1024);
            Ks[(c0 + 0) * 68 + t] = kv.x;
            Ks[(c0 + 1) * 68 + t] = kv.y;
            Ks[(c0 + 2) * 68 + t] = kv.z;
            Ks[(c0 + 3) * 68 + t] = kv.w;
            float4 vv = *(const float4*)(qkv + g + 2048);
            *(float4*)(Vs + t * 68 + c0) = vv;
        }
        __syncthreads();

        // S = (Q/8) @ K^T  (8x4 per thread)
        float s[8][4];
#pragma unroll
        for (int i = 0; i < 8; ++i)
#pragma unroll
            for (int j = 0; j < 4; ++j) s[i][j] = 0.f;

#pragma unroll 8
        for (int d = 0; d < 64; ++d) {
            float4 a0 = *(const float4*)(Qs + d * 132 + ty * 8);
            float4 a1 = *(const float4*)(Qs + d * 132 + ty * 8 + 4);
            float4 bf = *(const float4*)(Ks + d * 68 + tx * 4);
            float a[8] = {a0.x, a0.y, a0.z, a0.w, a1.x, a1.y, a1.z, a1.w};
            float bb[4] = {bf.x, bf.y, bf.z, bf.w};
#pragma unroll
            for (int i = 0; i < 8; ++i)
#pragma unroll
                for (int j = 0; j < 4; ++j)
                    s[i][j] += a[i] * bb[j];
        }

        // decay + online softmax
        const int kb = kt * 64 + tx * 4;
#pragma unroll
        for (int i = 0; i < 8; ++i) {
            const int qi = q0 + ty * 8 + i;
            float rmax = -INFINITY;
#pragma unroll
            for (int j = 0; j < 4; ++j) {
                int dist = qi - (kb + j);
                dist = dist < 0 ? -dist : dist;
                s[i][j] *= __expf(-absA * (float)dist);
                rmax = fmaxf(rmax, s[i][j]);
            }
#pragma unroll
            for (int mm = 8; mm >= 1; mm >>= 1)
                rmax = fmaxf(rmax, __shfl_xor_sync(0xffffffffu, rmax, mm));
            const float mn = fmaxf(m_i[i], rmax);
            const float alpha = __expf(m_i[i] - mn);
            m_i[i] = mn;
            float rsum = 0.f;
#pragma unroll
            for (int j = 0; j < 4; ++j) {
                float p = __expf(s[i][j] - mn);
                Ps[(tx * 4 + j) * 132 + ty * 8 + i] = p;
                rsum += p;
            }
#pragma unroll
            for (int mm = 8; mm >= 1; mm >>= 1)
                rsum += __shfl_xor_sync(0xffffffffu, rsum, mm);
            l_i[i] = l_i[i] * alpha + rsum;
            o[i][0] *= alpha; o[i][1] *= alpha;
            o[i][2] *= alpha; o[i][3] *= alpha;
        }
        __syncthreads();  // Ps visible

        // O += P @ V
#pragma unroll 8
        for (int t = 0; t < 64; ++t) {
            float4 a0 = *(const float4*)(Ps + t * 132 + ty * 8);
            float4 a1 = *(const float4*)(Ps + t * 132 + ty * 8 + 4);
            float4 bf = *(const float4*)(Vs + t * 68 + tx * 4);
            float a[8] = {a0.x, a0.y, a0.z, a0.w, a1.x, a1.y, a1.z, a1.w};
            float bb[4] = {bf.x, bf.y, bf.z, bf.w};
#pragma unroll
            for (int i = 0; i < 8; ++i)
#pragma unroll
                for (int j = 0; j < 4; ++j)
                    o[i][j] += a[i] * bb[j];
        }
    }

    // epilogue: normalize + write (b, s, h*D + d)
#pragma unroll
    for (int i = 0; i < 8; ++i) {
        const float inv = 1.0f / l_i[i];
        float4 st = {o[i][0] * inv, o[i][1] * inv, o[i][2] * inv, o[i][3] * inv};
        *(float4*)(outp + ((size_t)b * PS + q0 + ty * 8 + i) * PE + h * 64 + tx * 4) = st;
    }
}

// ---------------------------------------------------------------------------
extern "C" void kernel_launch(void* const* d_in, const int* in_sizes, int n_in,
                              void* d_out, int out_size)
{
    const float* x      = (const float*)d_in[0];
    const float* Wqkv_w = (const float*)d_in[1];
    const float* Wqkv_b = (const float*)d_in[2];
    const float* out_w  = (const float*)d_in[3];
    const float* out_b  = (const float*)d_in[4];
    const float* dd     = (const float*)d_in[5];
    float* outp = (float*)d_out;

    float* qkv;  float* attn;
    cudaGetSymbolAddress((void**)&qkv, g_qkv);
    cudaGetSymbolAddress((void**)&attn, g_attn);

    static_assert(PB * PS == 4096, "");
    const int SMEM_ATTN = 25600 * (int)sizeof(float);  // 102400 B
    cudaFuncSetAttribute(attn_kernel,
                         cudaFuncAttributeMaxDynamicSharedMemorySize, SMEM_ATTN);

    // 1) QKV projection: [4096,3072] = x[4096,1024] @ Wqkv^T + b
    gemm_nt_bias<<<dim3(3072 / 128, 4096 / 128), 256>>>(
        x, Wqkv_w, Wqkv_b, qkv, 4096, 3072, 1024);

    // 2) attention with distance decay -> [4096,1024]
    attn_kernel<<<dim3(PS / 128, PB * PH), 256, SMEM_ATTN>>>(qkv, attn, dd);

    // 3) output projection: out = attn @ out_w^T + out_b
    gemm_nt_bias<<<dim3(1024 / 128, 4096 / 128), 256>>>(
        attn, out_w, out_b, outp, 4096, 1024, 1024);
}

// round 6
// speedup vs baseline: 1.3095x; 1.3095x over previous
#include <cuda_runtime.h>
#include <cuda_fp16.h>
#include <math.h>
#include <stdint.h>

// Problem constants
#define PB 2
#define PS 2048
#define PE 1024
#define PH 16
#define PD 64

// ---------------------------------------------------------------------------
// Scratch (allocation-free rule: __device__ globals)
// ---------------------------------------------------------------------------
__device__ float g_qkv[PB * PS * 3 * PE];   // [B*S, 3E] fp32
__device__ float g_attn[PB * PS * PE];      // [B*S, E]  fp32
__device__ __half g_xhi[PB * PS * PE],  g_xlo[PB * PS * PE];
__device__ __half g_whi[3 * PE * PE],   g_wlo[3 * PE * PE];
__device__ __half g_owhi[PE * PE],      g_owlo[PE * PE];
__device__ __half g_ahi[PB * PS * PE],  g_alo[PB * PS * PE];

// ---------------------------------------------------------------------------
// PTX helpers (base ISA only: cp.async / ldmatrix / mma.sync — no tcgen05)
// ---------------------------------------------------------------------------
__device__ __forceinline__ uint32_t smem_u32(const void* p) {
    uint32_t a;
    asm("{ .reg .u64 t; cvta.to.shared.u64 t, %1; cvt.u32.u64 %0, t; }"
        : "=r"(a) : "l"(p));
    return a;
}

__device__ __forceinline__ void cp16(uint32_t s, const void* g) {
    asm volatile("cp.async.cg.shared.global [%0], [%1], 16;" :: "r"(s), "l"(g));
}
#define CP_COMMIT() asm volatile("cp.async.commit_group;" ::: "memory")
#define CP_WAIT1()  asm volatile("cp.async.wait_group 1;" ::: "memory")

#define LDSM_X4(r0, r1, r2, r3, a)                                            \
    asm volatile("ldmatrix.sync.aligned.m8n8.x4.shared.b16 {%0,%1,%2,%3}, [%4];" \
                 : "=r"(r0), "=r"(r1), "=r"(r2), "=r"(r3) : "r"(a))

#define MMA16816(c, a0, a1, a2, a3, b0, b1)                                   \
    asm volatile("mma.sync.aligned.m16n8k16.row.col.f32.f16.f16.f32 "         \
                 "{%0,%1,%2,%3}, {%4,%5,%6,%7}, {%8,%9}, {%0,%1,%2,%3};"      \
                 : "+f"((c)[0]), "+f"((c)[1]), "+f"((c)[2]), "+f"((c)[3])     \
                 : "r"(a0), "r"(a1), "r"(a2), "r"(a3), "r"(b0), "r"(b1))

// ---------------------------------------------------------------------------
// fp32 -> (fp16 hi, fp16 lo) split.  n4 = n/4 float4 work items.
// ---------------------------------------------------------------------------
__global__ void split_kernel(const float* __restrict__ in,
                             __half* __restrict__ hi, __half* __restrict__ lo,
                             int n4) {
    int i = blockIdx.x * blockDim.x + threadIdx.x;
    if (i >= n4) return;
    float4 v = ((const float4*)in)[i];
    __half h0 = __float2half_rn(v.x), h1 = __float2half_rn(v.y);
    __half h2 = __float2half_rn(v.z), h3 = __float2half_rn(v.w);
    __half l0 = __float2half_rn(v.x - __half2float(h0));
    __half l1 = __float2half_rn(v.y - __half2float(h1));
    __half l2 = __float2half_rn(v.z - __half2float(h2));
    __half l3 = __float2half_rn(v.w - __half2float(h3));
    ((__half2*)hi)[2 * i]     = __halves2half2(h0, h1);
    ((__half2*)hi)[2 * i + 1] = __halves2half2(h2, h3);
    ((__half2*)lo)[2 * i]     = __halves2half2(l0, l1);
    ((__half2*)lo)[2 * i + 1] = __halves2half2(l2, l3);
}

// ---------------------------------------------------------------------------
// Tensor-core NT GEMM via mma.sync, fp16 hi/lo split (3 MMAs per fragment):
//   C[M,N] = (Ahi+Alo)[M,K] * (Bhi+Blo)[N,K]^T + bias[N]   (lo*lo dropped)
// CTA 128x128, 256 thr (warps 2x4: warp tile 64x32). K-tile 32, double buffer.
// Smem per operand tile: 128 rows x 40 halves (pad) = 10240 B; stage 40960 B.
// Row stride 40*2=80B -> 16B-phase r*5 mod 8 is a permutation => ldmatrix
// conflict-free without swizzle.
// ---------------------------------------------------------------------------
#define ASTR 40
#define TILE_B   10240
#define STAGE_B  40960

__global__ __launch_bounds__(256) void gemm_tc(
    const __half* __restrict__ Ahi, const __half* __restrict__ Alo,
    const __half* __restrict__ Bhi, const __half* __restrict__ Blo,
    const float* __restrict__ bias, float* __restrict__ C,
    int N, int K)
{
    extern __shared__ __align__(16) __half sm[];
    const uint32_t sb = smem_u32(sm);

    const int tid = threadIdx.x;
    const int wid = tid >> 5, lane = tid & 31;
    const int wm = wid & 1, wn = wid >> 1;       // 2 x 4 warp grid
    const int m0 = blockIdx.y << 7;
    const int n0 = blockIdx.x << 7;
    const int T = K >> 5;                        // k-tiles of 32

    const __half* pAh = Ahi + (size_t)m0 * K;
    const __half* pAl = Alo + (size_t)m0 * K;
    const __half* pBh = Bhi + (size_t)n0 * K;
    const __half* pBl = Blo + (size_t)n0 * K;

    // loader mapping: row = tid/2 (0..127), chunks 2*(tid&1), +1  (16B each)
    const int lrow = tid >> 1;
    const int lch0 = (tid & 1) << 1;

    // ldmatrix per-lane invariants
    const int a_row = wm * 64 + (lane & 15);
    const int a_col = (lane >> 4) << 3;
    const int b_row = wn * 32 + (lane & 7) + ((lane >> 1) & 8);
    const int b_col = lane & 8;

    float acc[16][4];
#pragma unroll
    for (int i = 0; i < 16; ++i)
#pragma unroll
        for (int j = 0; j < 4; ++j) acc[i][j] = 0.f;

    // prologue: stages for k-tiles 0 and 1
#pragma unroll
    for (int t = 0; t < 2; ++t) {
        const uint32_t st = sb + t * STAGE_B;
        const int k0 = t * 32;
#pragma unroll
        for (int c = 0; c < 2; ++c) {
            const int ch = lch0 + c;
            const uint32_t soff = (uint32_t)(lrow * ASTR + ch * 8) * 2;
            const size_t goff = (size_t)lrow * K + k0 + ch * 8;
            cp16(st + soff,              pAh + goff);
            cp16(st + TILE_B + soff,     pAl + goff);
            cp16(st + 2 * TILE_B + soff, pBh + goff);
            cp16(st + 3 * TILE_B + soff, pBl + goff);
        }
        CP_COMMIT();
    }

    for (int t = 0; t < T; ++t) {
        CP_WAIT1();
        __syncthreads();

        const uint32_t st = sb + (t & 1) * STAGE_B;
#pragma unroll
        for (int k16 = 0; k16 < 2; ++k16) {
            const int kc = k16 * 16;
            // B fragments: 2 x4 loads cover 4 n-tiles, hi and lo
            uint32_t bh[8], bl[8];
#pragma unroll
            for (int p = 0; p < 2; ++p) {
                const uint32_t boff =
                    (uint32_t)((b_row + p * 16) * ASTR + kc + b_col) * 2;
                LDSM_X4(bh[4 * p], bh[4 * p + 1], bh[4 * p + 2], bh[4 * p + 3],
                        st + 2 * TILE_B + boff);
                LDSM_X4(bl[4 * p], bl[4 * p + 1], bl[4 * p + 2], bl[4 * p + 3],
                        st + 3 * TILE_B + boff);
            }
#pragma unroll
            for (int mt = 0; mt < 4; ++mt) {
                const uint32_t aoff =
                    (uint32_t)((a_row + mt * 16) * ASTR + kc + a_col) * 2;
                uint32_t ah0, ah1, ah2, ah3, al0, al1, al2, al3;
                LDSM_X4(ah0, ah1, ah2, ah3, st + aoff);
                LDSM_X4(al0, al1, al2, al3, st + TILE_B + aoff);
#pragma unroll
                for (int nt = 0; nt < 4; ++nt) {
                    // x4 B regs: even nt -> (r0,r1), odd nt -> (r2,r3)
                    const int bi = (nt >> 1) * 4 + (nt & 1) * 2;
                    float* c = acc[mt * 4 + nt];
                    MMA16816(c, ah0, ah1, ah2, ah3, bh[bi], bh[bi + 1]);
                    MMA16816(c, ah0, ah1, ah2, ah3, bl[bi], bl[bi + 1]);
                    MMA16816(c, al0, al1, al2, al3, bh[bi], bh[bi + 1]);
                }
            }
        }
        __syncthreads();

        if (t + 2 < T) {
            const uint32_t s2 = sb + (t & 1) * STAGE_B;
            const int k0 = (t + 2) * 32;
#pragma unroll
            for (int c = 0; c < 2; ++c) {
                const int ch = lch0 + c;
                const uint32_t soff = (uint32_t)(lrow * ASTR + ch * 8) * 2;
                const size_t goff = (size_t)lrow * K + k0 + ch * 8;
                cp16(s2 + soff,              pAh + goff);
                cp16(s2 + TILE_B + soff,     pAl + goff);
                cp16(s2 + 2 * TILE_B + soff, pBh + goff);
                cp16(s2 + 3 * TILE_B + soff, pBl + goff);
            }
        }
        CP_COMMIT();   // (possibly empty) keeps wait_group accounting aligned
    }

    // epilogue: c frag thread t -> rows (t/4, t/4+8), cols 2*(t%4)(+1)
    const int erow = lane >> 2;
    const int ecol = (lane & 3) << 1;
#pragma unroll
    for (int mt = 0; mt < 4; ++mt) {
#pragma unroll
        for (int nt = 0; nt < 4; ++nt) {
            const float* c = acc[mt * 4 + nt];
            const int col = n0 + wn * 32 + nt * 8 + ecol;
            const float b0 = bias[col], b1 = bias[col + 1];
            const size_t r0 = (size_t)(m0 + wm * 64 + mt * 16 + erow);
            float2 v0 = {c[0] + b0, c[1] + b1};
            float2 v1 = {c[2] + b0, c[3] + b1};
            *(float2*)(C + r0 * N + col)       = v0;
            *(float2*)(C + (r0 + 8) * N + col) = v1;
        }
    }
}

// ---------------------------------------------------------------------------
// Flash attention with multiplicative exponential distance decay (unchanged).
// ---------------------------------------------------------------------------
__global__ __launch_bounds__(256, 2) void attn_kernel(
    const float* __restrict__ qkv, float* __restrict__ outp,
    const float* __restrict__ dd)
{
    extern __shared__ float smf[];
    float* Qs = smf;              // 64*132
    float* Ks = smf + 8448;       // 64*68
    float* Vs = smf + 12800;      // 64*68
    float* Ps = smf + 17152;      // 64*132  (total 25600 floats)

    const int tid = threadIdx.x;
    const int ty = tid >> 4;
    const int tx = tid & 15;
    const int bh = blockIdx.y;
    const int b = bh >> 4;
    const int h = bh & 15;
    const int q0 = blockIdx.x * 128;
    const float absA = fabsf(dd[0]);

    const size_t qkv_b = (size_t)b * PS * 3072;
    const int c0 = tx << 2;
    const int rb = ty;

#pragma unroll
    for (int p = 0; p < 8; ++p) {
        const int r = rb + p * 16;
        float4 v = *(const float4*)(qkv + qkv_b + (size_t)(q0 + r) * 3072 + h * 64 + c0);
        Qs[(c0 + 0) * 132 + r] = v.x * 0.125f;
        Qs[(c0 + 1) * 132 + r] = v.y * 0.125f;
        Qs[(c0 + 2) * 132 + r] = v.z * 0.125f;
        Qs[(c0 + 3) * 132 + r] = v.w * 0.125f;
    }

    float m_i[8], l_i[8], o[8][4];
#pragma unroll
    for (int i = 0; i < 8; ++i) {
        m_i[i] = -INFINITY; l_i[i] = 0.f;
        o[i][0] = o[i][1] = o[i][2] = o[i][3] = 0.f;
    }

    for (int kt = 0; kt < 32; ++kt) {
        __syncthreads();
#pragma unroll
        for (int p = 0; p < 4; ++p) {
            const int t = rb + p * 16;
            const size_t g = qkv_b + (size_t)(kt * 64 + t) * 3072 + h * 64 + c0;
            float4 kv = *(const float4*)(qkv + g + 1024);
            Ks[(c0 + 0) * 68 + t] = kv.x;
            Ks[(c0 + 1) * 68 + t] = kv.y;
            Ks[(c0 + 2) * 68 + t] = kv.z;
            Ks[(c0 + 3) * 68 + t] = kv.w;
            float4 vv = *(const float4*)(qkv + g + 2048);
            *(float4*)(Vs + t * 68 + c0) = vv;
        }
        __syncthreads();

        float s[8][4];
#pragma unroll
        for (int i = 0; i < 8; ++i)
#pragma unroll
            for (int j = 0; j < 4; ++j) s[i][j] = 0.f;

#pragma unroll 8
        for (int d = 0; d < 64; ++d) {
            float4 a0 = *(const float4*)(Qs + d * 132 + ty * 8);
            float4 a1 = *(const float4*)(Qs + d * 132 + ty * 8 + 4);
            float4 bf = *(const float4*)(Ks + d * 68 + tx * 4);
            float a[8] = {a0.x, a0.y, a0.z, a0.w, a1.x, a1.y, a1.z, a1.w};
            float bb[4] = {bf.x, bf.y, bf.z, bf.w};
#pragma unroll
            for (int i = 0; i < 8; ++i)
#pragma unroll
                for (int j = 0; j < 4; ++j)
                    s[i][j] += a[i] * bb[j];
        }

        const int kb = kt * 64 + tx * 4;
#pragma unroll
        for (int i = 0; i < 8; ++i) {
            const int qi = q0 + ty * 8 + i;
            float rmax = -INFINITY;
#pragma unroll
            for (int j = 0; j < 4; ++j) {
                int dist = qi - (kb + j);
                dist = dist < 0 ? -dist : dist;
                s[i][j] *= __expf(-absA * (float)dist);
                rmax = fmaxf(rmax, s[i][j]);
            }
#pragma unroll
            for (int mm = 8; mm >= 1; mm >>= 1)
                rmax = fmaxf(rmax, __shfl_xor_sync(0xffffffffu, rmax, mm));
            const float mn = fmaxf(m_i[i], rmax);
            const float alpha = __expf(m_i[i] - mn);
            m_i[i] = mn;
            float rsum = 0.f;
#pragma unroll
            for (int j = 0; j < 4; ++j) {
                float p = __expf(s[i][j] - mn);
                Ps[(tx * 4 + j) * 132 + ty * 8 + i] = p;
                rsum += p;
            }
#pragma unroll
            for (int mm = 8; mm >= 1; mm >>= 1)
                rsum += __shfl_xor_sync(0xffffffffu, rsum, mm);
            l_i[i] = l_i[i] * alpha + rsum;
            o[i][0] *= alpha; o[i][1] *= alpha;
            o[i][2] *= alpha; o[i][3] *= alpha;
        }
        __syncthreads();

#pragma unroll 8
        for (int t = 0; t < 64; ++t) {
            float4 a0 = *(const float4*)(Ps + t * 132 + ty * 8);
            float4 a1 = *(const float4*)(Ps + t * 132 + ty * 8 + 4);
            float4 bf = *(const float4*)(Vs + t * 68 + tx * 4);
            float a[8] = {a0.x, a0.y, a0.z, a0.w, a1.x, a1.y, a1.z, a1.w};
            float bb[4] = {bf.x, bf.y, bf.z, bf.w};
#pragma unroll
            for (int i = 0; i < 8; ++i)
#pragma unroll
                for (int j = 0; j < 4; ++j)
                    o[i][j] += a[i] * bb[j];
        }
    }

#pragma unroll
    for (int i = 0; i < 8; ++i) {
        const float inv = 1.0f / l_i[i];
        float4 st = {o[i][0] * inv, o[i][1] * inv, o[i][2] * inv, o[i][3] * inv};
        *(float4*)(outp + ((size_t)b * PS + q0 + ty * 8 + i) * PE + h * 64 + tx * 4) = st;
    }
}

// ---------------------------------------------------------------------------
extern "C" void kernel_launch(void* const* d_in, const int* in_sizes, int n_in,
                              void* d_out, int out_size)
{
    const float* x      = (const float*)d_in[0];
    const float* Wqkv_w = (const float*)d_in[1];
    const float* Wqkv_b = (const float*)d_in[2];
    const float* out_w  = (const float*)d_in[3];
    const float* out_b  = (const float*)d_in[4];
    const float* dd     = (const float*)d_in[5];
    float* outp = (float*)d_out;

    float *qkv, *attn;
    __half *xhi, *xlo, *whi, *wlo, *owhi, *owlo, *ahi, *alo;
    cudaGetSymbolAddress((void**)&qkv,  g_qkv);
    cudaGetSymbolAddress((void**)&attn, g_attn);
    cudaGetSymbolAddress((void**)&xhi,  g_xhi);
    cudaGetSymbolAddress((void**)&xlo,  g_xlo);
    cudaGetSymbolAddress((void**)&whi,  g_whi);
    cudaGetSymbolAddress((void**)&wlo,  g_wlo);
    cudaGetSymbolAddress((void**)&owhi, g_owhi);
    cudaGetSymbolAddress((void**)&owlo, g_owlo);
    cudaGetSymbolAddress((void**)&ahi,  g_ahi);
    cudaGetSymbolAddress((void**)&alo,  g_alo);

    const int SMEM_GEMM = 2 * STAGE_B;            // 81920 B
    const int SMEM_ATTN = 25600 * (int)sizeof(float);
    cudaFuncSetAttribute(gemm_tc,
                         cudaFuncAttributeMaxDynamicSharedMemorySize, SMEM_GEMM);
    cudaFuncSetAttribute(attn_kernel,
                         cudaFuncAttributeMaxDynamicSharedMemorySize, SMEM_ATTN);

    // 0) fp32 -> fp16 hi/lo splits of the GEMM operands
    split_kernel<<<(PB * PS * PE / 4 + 255) / 256, 256>>>(x, xhi, xlo, PB * PS * PE / 4);
    split_kernel<<<(3 * PE * PE / 4 + 255) / 256, 256>>>(Wqkv_w, whi, wlo, 3 * PE * PE / 4);
    split_kernel<<<(PE * PE / 4 + 255) / 256, 256>>>(out_w, owhi, owlo, PE * PE / 4);

    // 1) QKV projection on tensor cores: qkv[4096,3072] = x @ Wqkv^T + b
    gemm_tc<<<dim3(3072 / 128, 4096 / 128), 256, SMEM_GEMM>>>(
        xhi, xlo, whi, wlo, Wqkv_b, qkv, 3072, 1024);

    // 2) attention with distance decay -> [4096,1024]
    attn_kernel<<<dim3(PS / 128, PB * PH), 256, SMEM_ATTN>>>(qkv, attn, dd);

    // 3) split attention output, then out projection on tensor cores
    split_kernel<<<(PB * PS * PE / 4 + 255) / 256, 256>>>(attn, ahi, alo, PB * PS * PE / 4);
    gemm_tc<<<dim3(1024 / 128, 4096 / 128), 256, SMEM_GEMM>>>(
        ahi, alo, owhi, owlo, out_b, outp, 1024, 1024);
}

// round 8
// speedup vs baseline: 2.4630x; 1.8809x over previous
#include <cuda_runtime.h>
#include <cuda_fp16.h>
#include <math.h>
#include <stdint.h>

// Problem constants
#define PB 2
#define PS 2048
#define PE 1024
#define PH 16
#define PD 64

// ---------------------------------------------------------------------------
// Scratch (allocation-free rule: __device__ globals)
// ---------------------------------------------------------------------------
__device__ __half g_qkvhi[PB * PS * 3 * PE], g_qkvlo[PB * PS * 3 * PE];
__device__ __half g_xhi[PB * PS * PE],  g_xlo[PB * PS * PE];
__device__ __half g_whi[3 * PE * PE],   g_wlo[3 * PE * PE];
__device__ __half g_owhi[PE * PE],      g_owlo[PE * PE];
__device__ __half g_ahi[PB * PS * PE],  g_alo[PB * PS * PE];

// ---------------------------------------------------------------------------
// PTX helpers (base ISA only: cp.async / ldmatrix / mma.sync)
// ---------------------------------------------------------------------------
__device__ __forceinline__ uint32_t smem_u32(const void* p) {
    uint32_t a;
    asm("{ .reg .u64 t; cvta.to.shared.u64 t, %1; cvt.u32.u64 %0, t; }"
        : "=r"(a) : "l"(p));
    return a;
}

__device__ __forceinline__ void cp16(uint32_t s, const void* g) {
    asm volatile("cp.async.cg.shared.global [%0], [%1], 16;" :: "r"(s), "l"(g));
}
#define CP_COMMIT() asm volatile("cp.async.commit_group;" ::: "memory")
#define CP_WAIT1()  asm volatile("cp.async.wait_group 1;" ::: "memory")
#define CP_WAIT0()  asm volatile("cp.async.wait_group 0;" ::: "memory")

#define LDSM_X4(r0, r1, r2, r3, a)                                            \
    asm volatile("ldmatrix.sync.aligned.m8n8.x4.shared.b16 {%0,%1,%2,%3}, [%4];" \
                 : "=r"(r0), "=r"(r1), "=r"(r2), "=r"(r3) : "r"(a))

#define LDSM_X4_T(r0, r1, r2, r3, a)                                          \
    asm volatile("ldmatrix.sync.aligned.m8n8.x4.trans.shared.b16 {%0,%1,%2,%3}, [%4];" \
                 : "=r"(r0), "=r"(r1), "=r"(r2), "=r"(r3) : "r"(a))

#define MMA16816(c, a0, a1, a2, a3, b0, b1)                                   \
    asm volatile("mma.sync.aligned.m16n8k16.row.col.f32.f16.f16.f32 "         \
                 "{%0,%1,%2,%3}, {%4,%5,%6,%7}, {%8,%9}, {%0,%1,%2,%3};"      \
                 : "+f"((c)[0]), "+f"((c)[1]), "+f"((c)[2]), "+f"((c)[3])     \
                 : "r"(a0), "r"(a1), "r"(a2), "r"(a3), "r"(b0), "r"(b1))

__device__ __forceinline__ uint32_t pack_h2(float f0, float f1) {
    __half2 hh = __halves2half2(__float2half_rn(f0), __float2half_rn(f1));
    return *reinterpret_cast<uint32_t*>(&hh);
}

// ---------------------------------------------------------------------------
// fp32 -> (fp16 hi, fp16 lo) split.
// ---------------------------------------------------------------------------
__global__ void split_kernel(const float* __restrict__ in,
                             __half* __restrict__ hi, __half* __restrict__ lo,
                             int n4) {
    int i = blockIdx.x * blockDim.x + threadIdx.x;
    if (i >= n4) return;
    float4 v = ((const float4*)in)[i];
    __half h0 = __float2half_rn(v.x), h1 = __float2half_rn(v.y);
    __half h2 = __float2half_rn(v.z), h3 = __float2half_rn(v.w);
    ((__half2*)hi)[2 * i]     = __halves2half2(h0, h1);
    ((__half2*)hi)[2 * i + 1] = __halves2half2(h2, h3);
    ((__half2*)lo)[2 * i] = __halves2half2(
        __float2half_rn(v.x - __half2float(h0)),
        __float2half_rn(v.y - __half2float(h1)));
    ((__half2*)lo)[2 * i + 1] = __halves2half2(
        __float2half_rn(v.z - __half2float(h2)),
        __float2half_rn(v.w - __half2float(h3)));
}

// ---------------------------------------------------------------------------
// Tensor-core NT GEMM via mma.sync, fp16 hi/lo split (3 MMAs per fragment).
// SPLIT=1: outputs hi/lo fp16 pair. SPLIT=0: fp32 output. (See R5 notes.)
// ---------------------------------------------------------------------------
#define ASTR 40
#define TILE_B   10240
#define STAGE_B  40960

template <int SPLIT>
__global__ __launch_bounds__(256) void gemm_tc(
    const __half* __restrict__ Ahi, const __half* __restrict__ Alo,
    const __half* __restrict__ Bhi, const __half* __restrict__ Blo,
    const float* __restrict__ bias, float* __restrict__ C,
    __half* __restrict__ Chi, __half* __restrict__ Clo,
    int N, int K)
{
    extern __shared__ __align__(16) __half sm[];
    const uint32_t sb = smem_u32(sm);

    const int tid = threadIdx.x;
    const int wid = tid >> 5, lane = tid & 31;
    const int wm = wid & 1, wn = wid >> 1;
    const int m0 = blockIdx.y << 7;
    const int n0 = blockIdx.x << 7;
    const int T = K >> 5;

    const __half* pAh = Ahi + (size_t)m0 * K;
    const __half* pAl = Alo + (size_t)m0 * K;
    const __half* pBh = Bhi + (size_t)n0 * K;
    const __half* pBl = Blo + (size_t)n0 * K;

    const int lrow = tid >> 1;
    const int lch0 = (tid & 1) << 1;

    const int a_row = wm * 64 + (lane & 15);
    const int a_col = (lane >> 4) << 3;
    const int b_row = wn * 32 + (lane & 7) + ((lane >> 1) & 8);
    const int b_col = lane & 8;

    float acc[16][4];
#pragma unroll
    for (int i = 0; i < 16; ++i)
#pragma unroll
        for (int j = 0; j < 4; ++j) acc[i][j] = 0.f;

#pragma unroll
    for (int t = 0; t < 2; ++t) {
        const uint32_t st = sb + t * STAGE_B;
        const int k0 = t * 32;
#pragma unroll
        for (int c = 0; c < 2; ++c) {
            const int ch = lch0 + c;
            const uint32_t soff = (uint32_t)(lrow * ASTR + ch * 8) * 2;
            const size_t goff = (size_t)lrow * K + k0 + ch * 8;
            cp16(st + soff,              pAh + goff);
            cp16(st + TILE_B + soff,     pAl + goff);
            cp16(st + 2 * TILE_B + soff, pBh + goff);
            cp16(st + 3 * TILE_B + soff, pBl + goff);
        }
        CP_COMMIT();
    }

    for (int t = 0; t < T; ++t) {
        CP_WAIT1();
        __syncthreads();

        const uint32_t st = sb + (t & 1) * STAGE_B;
#pragma unroll
        for (int k16 = 0; k16 < 2; ++k16) {
            const int kc = k16 * 16;
            uint32_t bh[8], bl[8];
#pragma unroll
            for (int p = 0; p < 2; ++p) {
                const uint32_t boff =
                    (uint32_t)((b_row + p * 16) * ASTR + kc + b_col) * 2;
                LDSM_X4(bh[4 * p], bh[4 * p + 1], bh[4 * p + 2], bh[4 * p + 3],
                        st + 2 * TILE_B + boff);
                LDSM_X4(bl[4 * p], bl[4 * p + 1], bl[4 * p + 2], bl[4 * p + 3],
                        st + 3 * TILE_B + boff);
            }
#pragma unroll
            for (int mt = 0; mt < 4; ++mt) {
                const uint32_t aoff =
                    (uint32_t)((a_row + mt * 16) * ASTR + kc + a_col) * 2;
                uint32_t ah0, ah1, ah2, ah3, al0, al1, al2, al3;
                LDSM_X4(ah0, ah1, ah2, ah3, st + aoff);
                LDSM_X4(al0, al1, al2, al3, st + TILE_B + aoff);
#pragma unroll
                for (int nt = 0; nt < 4; ++nt) {
                    const int bi = (nt >> 1) * 4 + (nt & 1) * 2;
                    float* c = acc[mt * 4 + nt];
                    MMA16816(c, ah0, ah1, ah2, ah3, bh[bi], bh[bi + 1]);
                    MMA16816(c, ah0, ah1, ah2, ah3, bl[bi], bl[bi + 1]);
                    MMA16816(c, al0, al1, al2, al3, bh[bi], bh[bi + 1]);
                }
            }
        }
        __syncthreads();

        if (t + 2 < T) {
            const uint32_t s2 = sb + (t & 1) * STAGE_B;
            const int k0 = (t + 2) * 32;
#pragma unroll
            for (int c = 0; c < 2; ++c) {
                const int ch = lch0 + c;
                const uint32_t soff = (uint32_t)(lrow * ASTR + ch * 8) * 2;
                const size_t goff = (size_t)lrow * K + k0 + ch * 8;
                cp16(s2 + soff,              pAh + goff);
                cp16(s2 + TILE_B + soff,     pAl + goff);
                cp16(s2 + 2 * TILE_B + soff, pBh + goff);
                cp16(s2 + 3 * TILE_B + soff, pBl + goff);
            }
        }
        CP_COMMIT();
    }

    const int erow = lane >> 2;
    const int ecol = (lane & 3) << 1;
#pragma unroll
    for (int mt = 0; mt < 4; ++mt) {
#pragma unroll
        for (int nt = 0; nt < 4; ++nt) {
            const float* c = acc[mt * 4 + nt];
            const int col = n0 + wn * 32 + nt * 8 + ecol;
            const float b0 = bias[col], b1 = bias[col + 1];
            const size_t r0 = (size_t)(m0 + wm * 64 + mt * 16 + erow);
            const float v00 = c[0] + b0, v01 = c[1] + b1;
            const float v10 = c[2] + b0, v11 = c[3] + b1;
            if (SPLIT) {
                __half h00 = __float2half_rn(v00), h01 = __float2half_rn(v01);
                __half h10 = __float2half_rn(v10), h11 = __float2half_rn(v11);
                *(__half2*)(Chi + r0 * N + col) = __halves2half2(h00, h01);
                *(__half2*)(Chi + (r0 + 8) * N + col) = __halves2half2(h10, h11);
                *(__half2*)(Clo + r0 * N + col) = __halves2half2(
                    __float2half_rn(v00 - __half2float(h00)),
                    __float2half_rn(v01 - __half2float(h01)));
                *(__half2*)(Clo + (r0 + 8) * N + col) = __halves2half2(
                    __float2half_rn(v10 - __half2float(h10)),
                    __float2half_rn(v11 - __half2float(h11)));
            } else {
                float2 w0 = {v00, v01}, w1 = {v10, v11};
                *(float2*)(C + r0 * N + col)       = w0;
                *(float2*)(C + (r0 + 8) * N + col) = w1;
            }
        }
    }
}

// ---------------------------------------------------------------------------
// Tensor-core flash attention with multiplicative exponential distance decay.
// CTA: 256 thr / 8 warps; 128 q-rows of one (b,h); 32 K/V tiles of 64.
// Q a-frags (hi+lo) register-resident. K/V hi/lo double-buffered via cp.async.
// Smem: 2 stages x {Kh,Kl,Vh,Vl} (64 x 72 halves each) + decay table.
// ---------------------------------------------------------------------------
#define VSTR  72
#define KT_B  9216               // 64*72*2
#define STG_B 36864              // 4 * KT_B
#define SMEM_ATTN (2 * STG_B + 2048 * 4)   // 81920 B

__global__ __launch_bounds__(256, 2) void attn_tc(
    const __half* __restrict__ qh_g, const __half* __restrict__ ql_g,
    __half* __restrict__ ahi, __half* __restrict__ alo,
    const float* __restrict__ dd)
{
    extern __shared__ __align__(16) char smraw[];
    const uint32_t sb = smem_u32(smraw);
    float* dec = (float*)(smraw + 2 * STG_B);

    const int tid = threadIdx.x;
    const int wid = tid >> 5, lane = tid & 31;
    const int b = blockIdx.y >> 4, h = blockIdx.y & 15;
    const int q0 = blockIdx.x << 7;
    const float absA = fabsf(dd[0]);

    // decay table: dec[d] = (1/8) * exp(-a*d)  (folds 1/sqrt(D))
#pragma unroll
    for (int k = 0; k < 8; ++k) {
        const int d = tid + k * 256;
        dec[d] = 0.125f * __expf(-absA * (float)d);
    }

    // ---- stage Q (hi/lo) into stage-0 area, ldmatrix into registers
#pragma unroll
    for (int rr = 0; rr < 4; ++rr) {
        const int c = tid + rr * 256;          // 0..1023
        const int row = c >> 3, c8 = c & 7;
        const uint32_t soff = (uint32_t)(row * VSTR + c8 * 8) * 2;
        const size_t g = ((size_t)(b * PS + q0 + row)) * 3072 + h * 64 + c8 * 8;
        cp16(sb + soff,         qh_g + g);
        cp16(sb + 18432 + soff, ql_g + g);
    }
    CP_COMMIT();
    CP_WAIT0();
    __syncthreads();

    uint32_t qh[16], ql[16];
    {
        const int arow = wid * 16 + (lane & 15);
        const int acol = (lane >> 4) << 3;
#pragma unroll
        for (int kf = 0; kf < 4; ++kf) {
            const uint32_t off = (uint32_t)(arow * VSTR + kf * 16 + acol) * 2;
            LDSM_X4(qh[kf * 4], qh[kf * 4 + 1], qh[kf * 4 + 2], qh[kf * 4 + 3],
                    sb + off);
            LDSM_X4(ql[kf * 4], ql[kf * 4 + 1], ql[kf * 4 + 2], ql[kf * 4 + 3],
                    sb + 18432 + off);
        }
    }
    __syncthreads();

    // prologue: K/V tiles 0 and 1
#pragma unroll
    for (int t = 0; t < 2; ++t) {
        const uint32_t st = sb + t * STG_B;
#pragma unroll
        for (int rr = 0; rr < 2; ++rr) {
            const int c = tid + rr * 256;
            const int row = c >> 3, c8 = c & 7;
            const uint32_t soff = (uint32_t)(row * VSTR + c8 * 8) * 2;
            const size_t g =
                ((size_t)(b * PS + t * 64 + row)) * 3072 + h * 64 + c8 * 8;
            cp16(st + soff,            qh_g + g + 1024);   // K hi
            cp16(st + KT_B + soff,     ql_g + g + 1024);   // K lo
            cp16(st + 2 * KT_B + soff, qh_g + g + 2048);   // V hi
            cp16(st + 3 * KT_B + soff, ql_g + g + 2048);   // V lo
        }
        CP_COMMIT();
    }

    const int brow = (lane & 7) + ((lane >> 1) & 8);
    const int bcol = lane & 8;
    const int trow = lane & 15;
    const int tcol = (lane >> 4) << 3;

    float m[2] = {-INFINITY, -INFINITY};
    float l[2] = {0.f, 0.f};
    float o[32];
#pragma unroll
    for (int i = 0; i < 32; ++i) o[i] = 0.f;

    const int r0g = q0 + wid * 16 + (lane >> 2);
    const int jb0 = 2 * (lane & 3);

    for (int kt = 0; kt < 32; ++kt) {
        CP_WAIT1();
        __syncthreads();
        const uint32_t st = sb + (kt & 1) * STG_B;

        // ---- S = Q * K^T (3-term split), per-warp 16x64
        float s[32];
#pragma unroll
        for (int i = 0; i < 32; ++i) s[i] = 0.f;

#pragma unroll
        for (int kf = 0; kf < 4; ++kf) {
            const uint32_t* qa = qh + kf * 4;
            const uint32_t* qb = ql + kf * 4;
#pragma unroll
            for (int p = 0; p < 4; ++p) {
                const uint32_t boff =
                    (uint32_t)((brow + p * 16) * VSTR + kf * 16 + bcol) * 2;
                uint32_t kh0, kh1, kh2, kh3, kl0, kl1, kl2, kl3;
                LDSM_X4(kh0, kh1, kh2, kh3, st + boff);
                LDSM_X4(kl0, kl1, kl2, kl3, st + KT_B + boff);
                float* c0 = s + (2 * p) * 4;
                float* c1 = s + (2 * p + 1) * 4;
                MMA16816(c0, qa[0], qa[1], qa[2], qa[3], kh0, kh1);
                MMA16816(c0, qa[0], qa[1], qa[2], qa[3], kl0, kl1);
                MMA16816(c0, qb[0], qb[1], qb[2], qb[3], kh0, kh1);
                MMA16816(c1, qa[0], qa[1], qa[2], qa[3], kh2, kh3);
                MMA16816(c1, qa[0], qa[1], qa[2], qa[3], kl2, kl3);
                MMA16816(c1, qb[0], qb[1], qb[2], qb[3], kh2, kh3);
            }
        }

        // ---- decay + online softmax (rows spread over lane%4 groups)
#pragma unroll
        for (int r = 0; r < 2; ++r) {
            const int iq = r0g + r * 8;
            float rmax = -INFINITY;
#pragma unroll
            for (int nt = 0; nt < 8; ++nt) {
#pragma unroll
                for (int e = 0; e < 2; ++e) {
                    const int j = kt * 64 + nt * 8 + jb0 + e;
                    int di = iq - j; di = di < 0 ? -di : di;
                    const float v = s[nt * 4 + r * 2 + e] * dec[di];
                    s[nt * 4 + r * 2 + e] = v;
                    rmax = fmaxf(rmax, v);
                }
            }
            rmax = fmaxf(rmax, __shfl_xor_sync(0xffffffffu, rmax, 1));
            rmax = fmaxf(rmax, __shfl_xor_sync(0xffffffffu, rmax, 2));
            const float mn = fmaxf(m[r], rmax);
            const float alpha = __expf(m[r] - mn);
            m[r] = mn;
            float rsum = 0.f;
#pragma unroll
            for (int nt = 0; nt < 8; ++nt) {
#pragma unroll
                for (int e = 0; e < 2; ++e) {
                    const float p = __expf(s[nt * 4 + r * 2 + e] - mn);
                    s[nt * 4 + r * 2 + e] = p;
                    rsum += p;
                }
            }
            rsum += __shfl_xor_sync(0xffffffffu, rsum, 1);
            rsum += __shfl_xor_sync(0xffffffffu, rsum, 2);
            l[r] = l[r] * alpha + rsum;
#pragma unroll
            for (int nt = 0; nt < 8; ++nt) {
                o[nt * 4 + r * 2]     *= alpha;
                o[nt * 4 + r * 2 + 1] *= alpha;
            }
        }

        // ---- pack P into A-frags (hi + residual lo)
        uint32_t ph[16], pl[16];
#pragma unroll
        for (int kf = 0; kf < 4; ++kf) {
#pragma unroll
            for (int q = 0; q < 4; ++q) {
                const int nt = 2 * kf + (q >> 1);
                const int base = nt * 4 + (q & 1) * 2;
                const float f0 = s[base], f1 = s[base + 1];
                const __half h0 = __float2half_rn(f0);
                const __half h1 = __float2half_rn(f1);
                __half2 hh = __halves2half2(h0, h1);
                ph[kf * 4 + q] = *reinterpret_cast<uint32_t*>(&hh);
                __half2 llv = __halves2half2(
                    __float2half_rn(f0 - __half2float(h0)),
                    __float2half_rn(f1 - __half2float(h1)));
                pl[kf * 4 + q] = *reinterpret_cast<uint32_t*>(&llv);
            }
        }

        // ---- O += P * V   (V via ldmatrix.trans from natural [t][d])
#pragma unroll
        for (int tf = 0; tf < 4; ++tf) {
            const uint32_t* pa = ph + tf * 4;
            const uint32_t* pb = pl + tf * 4;
#pragma unroll
            for (int p = 0; p < 4; ++p) {
                const uint32_t boff =
                    (uint32_t)((tf * 16 + trow) * VSTR + p * 16 + tcol) * 2;
                uint32_t vh0, vh1, vh2, vh3, vl0, vl1, vl2, vl3;
                LDSM_X4_T(vh0, vh1, vh2, vh3, st + 2 * KT_B + boff);
                LDSM_X4_T(vl0, vl1, vl2, vl3, st + 3 * KT_B + boff);
                float* c0 = o + (2 * p) * 4;
                float* c1 = o + (2 * p + 1) * 4;
                MMA16816(c0, pa[0], pa[1], pa[2], pa[3], vh0, vh1);
                MMA16816(c0, pa[0], pa[1], pa[2], pa[3], vl0, vl1);
                MMA16816(c0, pb[0], pb[1], pb[2], pb[3], vh0, vh1);
                MMA16816(c1, pa[0], pa[1], pa[2], pa[3], vh2, vh3);
                MMA16816(c1, pa[0], pa[1], pa[2], pa[3], vl2, vl3);
                MMA16816(c1, pb[0], pb[1], pb[2], pb[3], vh2, vh3);
            }
        }

        __syncthreads();
        if (kt + 2 < 32) {
            const uint32_t s2 = sb + (kt & 1) * STG_B;
#pragma unroll
            for (int rr = 0; rr < 2; ++rr) {
                const int c = tid + rr * 256;
                const int row = c >> 3, c8 = c & 7;
                const uint32_t soff = (uint32_t)(row * VSTR + c8 * 8) * 2;
                const size_t g =
                    ((size_t)(b * PS + (kt + 2) * 64 + row)) * 3072 + h * 64 + c8 * 8;
                cp16(s2 + soff,            qh_g + g + 1024);
                cp16(s2 + KT_B + soff,     ql_g + g + 1024);
                cp16(s2 + 2 * KT_B + soff, qh_g + g + 2048);
                cp16(s2 + 3 * KT_B + soff, ql_g + g + 2048);
            }
        }
        CP_COMMIT();
    }

    // ---- epilogue: normalize, write hi/lo for the out-projection
    const float inv0 = 1.0f / l[0], inv1 = 1.0f / l[1];
#pragma unroll
    for (int r = 0; r < 2; ++r) {
        const float inv = r ? inv1 : inv0;
        const size_t rowoff =
            ((size_t)(b * PS + r0g + r * 8)) * PE + h * 64 + jb0;
#pragma unroll
        for (int nt = 0; nt < 8; ++nt) {
            const float v0 = o[nt * 4 + r * 2] * inv;
            const float v1 = o[nt * 4 + r * 2 + 1] * inv;
            const __half h0 = __float2half_rn(v0);
            const __half h1 = __float2half_rn(v1);
            *(__half2*)(ahi + rowoff + nt * 8) = __halves2half2(h0, h1);
            *(__half2*)(alo + rowoff + nt * 8) = __halves2half2(
                __float2half_rn(v0 - __half2float(h0)),
                __float2half_rn(v1 - __half2float(h1)));
        }
    }
}

// ---------------------------------------------------------------------------
extern "C" void kernel_launch(void* const* d_in, const int* in_sizes, int n_in,
                              void* d_out, int out_size)
{
    const float* x      = (const float*)d_in[0];
    const float* Wqkv_w = (const float*)d_in[1];
    const float* Wqkv_b = (const float*)d_in[2];
    const float* out_w  = (const float*)d_in[3];
    const float* out_b  = (const float*)d_in[4];
    const float* dd     = (const float*)d_in[5];
    float* outp = (float*)d_out;

    __half *qkvhi, *qkvlo, *xhi, *xlo, *whi, *wlo, *owhi, *owlo, *ahi, *alo;
    cudaGetSymbolAddress((void**)&qkvhi, g_qkvhi);
    cudaGetSymbolAddress((void**)&qkvlo, g_qkvlo);
    cudaGetSymbolAddress((void**)&xhi,  g_xhi);
    cudaGetSymbolAddress((void**)&xlo,  g_xlo);
    cudaGetSymbolAddress((void**)&whi,  g_whi);
    cudaGetSymbolAddress((void**)&wlo,  g_wlo);
    cudaGetSymbolAddress((void**)&owhi, g_owhi);
    cudaGetSymbolAddress((void**)&owlo, g_owlo);
    cudaGetSymbolAddress((void**)&ahi,  g_ahi);
    cudaGetSymbolAddress((void**)&alo,  g_alo);

    const int SMEM_GEMM = 2 * STAGE_B;            // 81920 B
    cudaFuncSetAttribute(gemm_tc<1>,
                         cudaFuncAttributeMaxDynamicSharedMemorySize, SMEM_GEMM);
    cudaFuncSetAttribute(gemm_tc<0>,
                         cudaFuncAttributeMaxDynamicSharedMemorySize, SMEM_GEMM);
    cudaFuncSetAttribute(attn_tc,
                         cudaFuncAttributeMaxDynamicSharedMemorySize, SMEM_ATTN);

    // 0) fp32 -> fp16 hi/lo splits of the input operands
    split_kernel<<<(PB * PS * PE / 4 + 255) / 256, 256>>>(x, xhi, xlo, PB * PS * PE / 4);
    split_kernel<<<(3 * PE * PE / 4 + 255) / 256, 256>>>(Wqkv_w, whi, wlo, 3 * PE * PE / 4);
    split_kernel<<<(PE * PE / 4 + 255) / 256, 256>>>(out_w, owhi, owlo, PE * PE / 4);

    // 1) QKV projection, epilogue writes hi/lo fp16 directly
    gemm_tc<1><<<dim3(3072 / 128, 4096 / 128), 256, SMEM_GEMM>>>(
        xhi, xlo, whi, wlo, Wqkv_b, nullptr, qkvhi, qkvlo, 3072, 1024);

    // 2) tensor-core flash attention with distance decay -> hi/lo
    attn_tc<<<dim3(PS / 128, PB * PH), 256, SMEM_ATTN>>>(
        qkvhi, qkvlo, ahi, alo, dd);

    // 3) output projection -> fp32 result
    gemm_tc<0><<<dim3(1024 / 128, 4096 / 128), 256, SMEM_GEMM>>>(
        ahi, alo, owhi, owlo, out_b, outp, nullptr, nullptr, 1024, 1024);
}

// round 9
// speedup vs baseline: 2.7516x; 1.1172x over previous
#include <cuda_runtime.h>
#include <cuda_fp16.h>
#include <math.h>
#include <stdint.h>

// Problem constants
#define PB 2
#define PS 2048
#define PE 1024
#define PH 16
#define PD 64

// ---------------------------------------------------------------------------
// Scratch (allocation-free rule: __device__ globals)
// ---------------------------------------------------------------------------
__device__ __half g_qkvhi[PB * PS * 3 * PE], g_qkvlo[PB * PS * 3 * PE];
__device__ __half g_xhi[PB * PS * PE],  g_xlo[PB * PS * PE];
__device__ __half g_whi[3 * PE * PE],   g_wlo[3 * PE * PE];
__device__ __half g_owhi[PE * PE],      g_owlo[PE * PE];
__device__ __half g_ahi[PB * PS * PE],  g_alo[PB * PS * PE];

// ---------------------------------------------------------------------------
// PTX helpers (base ISA only: cp.async / ldmatrix / mma.sync)
// ---------------------------------------------------------------------------
__device__ __forceinline__ uint32_t smem_u32(const void* p) {
    uint32_t a;
    asm("{ .reg .u64 t; cvta.to.shared.u64 t, %1; cvt.u32.u64 %0, t; }"
        : "=r"(a) : "l"(p));
    return a;
}

__device__ __forceinline__ void cp16(uint32_t s, const void* g) {
    asm volatile("cp.async.cg.shared.global [%0], [%1], 16;" :: "r"(s), "l"(g));
}
#define CP_COMMIT() asm volatile("cp.async.commit_group;" ::: "memory")
#define CP_WAIT1()  asm volatile("cp.async.wait_group 1;" ::: "memory")
#define CP_WAIT0()  asm volatile("cp.async.wait_group 0;" ::: "memory")

#define LDSM_X4(r0, r1, r2, r3, a)                                            \
    asm volatile("ldmatrix.sync.aligned.m8n8.x4.shared.b16 {%0,%1,%2,%3}, [%4];" \
                 : "=r"(r0), "=r"(r1), "=r"(r2), "=r"(r3) : "r"(a))

#define LDSM_X4_T(r0, r1, r2, r3, a)                                          \
    asm volatile("ldmatrix.sync.aligned.m8n8.x4.trans.shared.b16 {%0,%1,%2,%3}, [%4];" \
                 : "=r"(r0), "=r"(r1), "=r"(r2), "=r"(r3) : "r"(a))

#define MMA16816(c, a0, a1, a2, a3, b0, b1)                                   \
    asm volatile("mma.sync.aligned.m16n8k16.row.col.f32.f16.f16.f32 "         \
                 "{%0,%1,%2,%3}, {%4,%5,%6,%7}, {%8,%9}, {%0,%1,%2,%3};"      \
                 : "+f"((c)[0]), "+f"((c)[1]), "+f"((c)[2]), "+f"((c)[3])     \
                 : "r"(a0), "r"(a1), "r"(a2), "r"(a3), "r"(b0), "r"(b1))

// XOR swizzles for conflict-free ldmatrix on unpadded rows
#define SW64B(o)  ((o) ^ (((o) >> 3) & 0x30))   // 64B rows (GEMM k-tile 32)
#define SW128B(o) ((o) ^ (((o) >> 3) & 0x70))   // 128B rows (attention d=64)

// ---------------------------------------------------------------------------
// fp32 -> (fp16 hi, fp16 lo) split.
// ---------------------------------------------------------------------------
__global__ void split_kernel(const float* __restrict__ in,
                             __half* __restrict__ hi, __half* __restrict__ lo,
                             int n4) {
    int i = blockIdx.x * blockDim.x + threadIdx.x;
    if (i >= n4) return;
    float4 v = ((const float4*)in)[i];
    __half h0 = __float2half_rn(v.x), h1 = __float2half_rn(v.y);
    __half h2 = __float2half_rn(v.z), h3 = __float2half_rn(v.w);
    ((__half2*)hi)[2 * i]     = __halves2half2(h0, h1);
    ((__half2*)hi)[2 * i + 1] = __halves2half2(h2, h3);
    ((__half2*)lo)[2 * i] = __halves2half2(
        __float2half_rn(v.x - __half2float(h0)),
        __float2half_rn(v.y - __half2float(h1)));
    ((__half2*)lo)[2 * i + 1] = __halves2half2(
        __float2half_rn(v.z - __half2float(h2)),
        __float2half_rn(v.w - __half2float(h3)));
}

// ---------------------------------------------------------------------------
// Tensor-core NT GEMM, fp16 hi/lo split (3 MMAs/fragment), 3-stage pipeline,
// single barrier per k-tile, SW64 swizzled unpadded smem.
// CTA 128x128, 256 thr (warps 2x4: warp tile 64x32). K-tile 32.
// Tile = 128 rows x 64B = 8192 B; stage {Ah,Al,Bh,Bl} = 32768 B; 3 stages.
// ---------------------------------------------------------------------------
#define GTILE_B  8192
#define GSTAGE_B 32768
#define SMEM_GEMM (3 * GSTAGE_B)   // 98304 B -> 2 CTAs/SM

template <int SPLIT>
__global__ __launch_bounds__(256, 2) void gemm_tc(
    const __half* __restrict__ Ahi, const __half* __restrict__ Alo,
    const __half* __restrict__ Bhi, const __half* __restrict__ Blo,
    const float* __restrict__ bias, float* __restrict__ C,
    __half* __restrict__ Chi, __half* __restrict__ Clo,
    int N, int K)
{
    extern __shared__ __align__(16) __half sm[];
    const uint32_t sb = smem_u32(sm);

    const int tid = threadIdx.x;
    const int wid = tid >> 5, lane = tid & 31;
    const int wm = wid & 1, wn = wid >> 1;
    const int m0 = blockIdx.y << 7;
    const int n0 = blockIdx.x << 7;
    const int T = K >> 5;

    const __half* pAh = Ahi + (size_t)m0 * K;
    const __half* pAl = Alo + (size_t)m0 * K;
    const __half* pBh = Bhi + (size_t)n0 * K;
    const __half* pBl = Blo + (size_t)n0 * K;

    // loader: row = tid/2, two 16B chunks of the 64B row
    const int lrow = tid >> 1;
    const int lch0 = (tid & 1) << 1;

    const int a_row = wm * 64 + (lane & 15);
    const int a_col = (lane >> 4) << 3;                 // halves
    const int b_row = wn * 32 + (lane & 7) + ((lane >> 1) & 8);
    const int b_col = lane & 8;                         // halves

    float acc[16][4];
#pragma unroll
    for (int i = 0; i < 16; ++i)
#pragma unroll
        for (int j = 0; j < 4; ++j) acc[i][j] = 0.f;

    // prologue: tiles 0, 1
#pragma unroll
    for (int t = 0; t < 2; ++t) {
        const uint32_t st = sb + t * GSTAGE_B;
        const int k0 = t * 32;
#pragma unroll
        for (int c = 0; c < 2; ++c) {
            const int ch = lch0 + c;
            const uint32_t so = SW64B((uint32_t)(lrow * 64 + ch * 16));
            const size_t goff = (size_t)lrow * K + k0 + ch * 8;
            cp16(st + so,              pAh + goff);
            cp16(st + GTILE_B + so,    pAl + goff);
            cp16(st + 2 * GTILE_B + so, pBh + goff);
            cp16(st + 3 * GTILE_B + so, pBl + goff);
        }
        CP_COMMIT();
    }

    int rd = 0, wr = 2;   // stage indices mod 3
    for (int t = 0; t < T; ++t) {
        CP_WAIT1();
        __syncthreads();

        if (t + 2 < T) {
            const uint32_t s2 = sb + wr * GSTAGE_B;
            const int k0 = (t + 2) * 32;
#pragma unroll
            for (int c = 0; c < 2; ++c) {
                const int ch = lch0 + c;
                const uint32_t so = SW64B((uint32_t)(lrow * 64 + ch * 16));
                const size_t goff = (size_t)lrow * K + k0 + ch * 8;
                cp16(s2 + so,               pAh + goff);
                cp16(s2 + GTILE_B + so,     pAl + goff);
                cp16(s2 + 2 * GTILE_B + so, pBh + goff);
                cp16(s2 + 3 * GTILE_B + so, pBl + goff);
            }
            CP_COMMIT();
        }

        const uint32_t st = sb + rd * GSTAGE_B;
#pragma unroll
        for (int k16 = 0; k16 < 2; ++k16) {
            const int kc = k16 * 16;                    // halves
            uint32_t bh[8], bl[8];
#pragma unroll
            for (int p = 0; p < 2; ++p) {
                const uint32_t bo = SW64B(
                    (uint32_t)((b_row + p * 16) * 64 + (kc + b_col) * 2));
                LDSM_X4(bh[4 * p], bh[4 * p + 1], bh[4 * p + 2], bh[4 * p + 3],
                        st + 2 * GTILE_B + bo);
                LDSM_X4(bl[4 * p], bl[4 * p + 1], bl[4 * p + 2], bl[4 * p + 3],
                        st + 3 * GTILE_B + bo);
            }
#pragma unroll
            for (int mt = 0; mt < 4; ++mt) {
                const uint32_t ao = SW64B(
                    (uint32_t)((a_row + mt * 16) * 64 + (kc + a_col) * 2));
                uint32_t ah0, ah1, ah2, ah3, al0, al1, al2, al3;
                LDSM_X4(ah0, ah1, ah2, ah3, st + ao);
                LDSM_X4(al0, al1, al2, al3, st + GTILE_B + ao);
#pragma unroll
                for (int nt = 0; nt < 4; ++nt) {
                    const int bi = (nt >> 1) * 4 + (nt & 1) * 2;
                    float* c = acc[mt * 4 + nt];
                    MMA16816(c, ah0, ah1, ah2, ah3, bh[bi], bh[bi + 1]);
                    MMA16816(c, ah0, ah1, ah2, ah3, bl[bi], bl[bi + 1]);
                    MMA16816(c, al0, al1, al2, al3, bh[bi], bh[bi + 1]);
                }
            }
        }
        rd = rd == 2 ? 0 : rd + 1;
        wr = wr == 2 ? 0 : wr + 1;
    }

    const int erow = lane >> 2;
    const int ecol = (lane & 3) << 1;
#pragma unroll
    for (int mt = 0; mt < 4; ++mt) {
#pragma unroll
        for (int nt = 0; nt < 4; ++nt) {
            const float* c = acc[mt * 4 + nt];
            const int col = n0 + wn * 32 + nt * 8 + ecol;
            const float b0 = bias[col], b1 = bias[col + 1];
            const size_t r0 = (size_t)(m0 + wm * 64 + mt * 16 + erow);
            const float v00 = c[0] + b0, v01 = c[1] + b1;
            const float v10 = c[2] + b0, v11 = c[3] + b1;
            if (SPLIT) {
                __half h00 = __float2half_rn(v00), h01 = __float2half_rn(v01);
                __half h10 = __float2half_rn(v10), h11 = __float2half_rn(v11);
                *(__half2*)(Chi + r0 * N + col) = __halves2half2(h00, h01);
                *(__half2*)(Chi + (r0 + 8) * N + col) = __halves2half2(h10, h11);
                *(__half2*)(Clo + r0 * N + col) = __halves2half2(
                    __float2half_rn(v00 - __half2float(h00)),
                    __float2half_rn(v01 - __half2float(h01)));
                *(__half2*)(Clo + (r0 + 8) * N + col) = __halves2half2(
                    __float2half_rn(v10 - __half2float(h10)),
                    __float2half_rn(v11 - __half2float(h11)));
            } else {
                float2 w0 = {v00, v01}, w1 = {v10, v11};
                *(float2*)(C + r0 * N + col)       = w0;
                *(float2*)(C + (r0 + 8) * N + col) = w1;
            }
        }
    }
}

// ---------------------------------------------------------------------------
// Tensor-core flash attention, 3-stage single-barrier K/V pipeline,
// SW128 swizzled unpadded smem (128B rows), decay via smem table.
// Tile = 64 rows x 128B = 8192 B; stage {Kh,Kl,Vh,Vl} = 32768 B; 3 stages.
// ---------------------------------------------------------------------------
#define AT_B   8192
#define ASTG_B 32768
#define SMEM_ATTN (3 * ASTG_B + 2048 * 4)   // 106496 B -> 2 CTAs/SM

__global__ __launch_bounds__(256, 2) void attn_tc(
    const __half* __restrict__ qh_g, const __half* __restrict__ ql_g,
    __half* __restrict__ ahi, __half* __restrict__ alo,
    const float* __restrict__ dd)
{
    extern __shared__ __align__(16) char smraw[];
    const uint32_t sb = smem_u32(smraw);
    float* dec = (float*)(smraw + 3 * ASTG_B);

    const int tid = threadIdx.x;
    const int wid = tid >> 5, lane = tid & 31;
    const int b = blockIdx.y >> 4, h = blockIdx.y & 15;
    const int q0 = blockIdx.x << 7;
    const float absA = fabsf(dd[0]);

    // decay table: dec[d] = (1/8) * exp(-a*d)
#pragma unroll
    for (int k = 0; k < 8; ++k) {
        const int d = tid + k * 256;
        dec[d] = 0.125f * __expf(-absA * (float)d);
    }

    // ---- stage Q (hi at sb, lo at sb+16384), extract a-frags
#pragma unroll
    for (int rr = 0; rr < 4; ++rr) {
        const int c = tid + rr * 256;          // 0..1023 chunks
        const int row = c >> 3, ch = c & 7;
        const uint32_t so = SW128B((uint32_t)(row * 128 + ch * 16));
        const size_t g = ((size_t)(b * PS + q0 + row)) * 3072 + h * 64 + ch * 8;
        cp16(sb + so,         qh_g + g);
        cp16(sb + 16384 + so, ql_g + g);
    }
    CP_COMMIT();
    CP_WAIT0();
    __syncthreads();

    uint32_t qh[16], ql[16];
    {
        const int arow = wid * 16 + (lane & 15);
        const int acol = (lane >> 4) << 3;
#pragma unroll
        for (int kf = 0; kf < 4; ++kf) {
            const uint32_t o = SW128B(
                (uint32_t)(arow * 128 + (kf * 16 + acol) * 2));
            LDSM_X4(qh[kf * 4], qh[kf * 4 + 1], qh[kf * 4 + 2], qh[kf * 4 + 3],
                    sb + o);
            LDSM_X4(ql[kf * 4], ql[kf * 4 + 1], ql[kf * 4 + 2], ql[kf * 4 + 3],
                    sb + 16384 + o);
        }
    }
    __syncthreads();    // Q reads done before K/V prologue overwrites stages

    // prologue: K/V tiles 0, 1
#pragma unroll
    for (int t = 0; t < 2; ++t) {
        const uint32_t st = sb + t * ASTG_B;
#pragma unroll
        for (int rr = 0; rr < 2; ++rr) {
            const int c = tid + rr * 256;      // 0..511 chunks
            const int row = c >> 3, ch = c & 7;
            const uint32_t so = SW128B((uint32_t)(row * 128 + ch * 16));
            const size_t g =
                ((size_t)(b * PS + t * 64 + row)) * 3072 + h * 64 + ch * 8;
            cp16(st + so,            qh_g + g + 1024);   // K hi
            cp16(st + AT_B + so,     ql_g + g + 1024);   // K lo
            cp16(st + 2 * AT_B + so, qh_g + g + 2048);   // V hi
            cp16(st + 3 * AT_B + so, ql_g + g + 2048);   // V lo
        }
        CP_COMMIT();
    }

    const int brow = (lane & 7) + ((lane >> 1) & 8);
    const int bcol = lane & 8;
    const int trow = lane & 15;
    const int tcol = (lane >> 4) << 3;

    float m[2] = {-INFINITY, -INFINITY};
    float l[2] = {0.f, 0.f};
    float o[32];
#pragma unroll
    for (int i = 0; i < 32; ++i) o[i] = 0.f;

    const int r0g = q0 + wid * 16 + (lane >> 2);
    const int jb0 = 2 * (lane & 3);

    int rd = 0, wr = 2;
    for (int kt = 0; kt < 32; ++kt) {
        CP_WAIT1();
        __syncthreads();

        if (kt + 2 < 32) {
            const uint32_t s2 = sb + wr * ASTG_B;
#pragma unroll
            for (int rr = 0; rr < 2; ++rr) {
                const int c = tid + rr * 256;
                const int row = c >> 3, ch = c & 7;
                const uint32_t so = SW128B((uint32_t)(row * 128 + ch * 16));
                const size_t g =
                    ((size_t)(b * PS + (kt + 2) * 64 + row)) * 3072 + h * 64 + ch * 8;
                cp16(s2 + so,            qh_g + g + 1024);
                cp16(s2 + AT_B + so,     ql_g + g + 1024);
                cp16(s2 + 2 * AT_B + so, qh_g + g + 2048);
                cp16(s2 + 3 * AT_B + so, ql_g + g + 2048);
            }
            CP_COMMIT();
        }

        const uint32_t st = sb + rd * ASTG_B;

        // ---- S = Q * K^T (3-term split), per-warp 16x64
        float s[32];
#pragma unroll
        for (int i = 0; i < 32; ++i) s[i] = 0.f;

#pragma unroll
        for (int kf = 0; kf < 4; ++kf) {
            const uint32_t* qa = qh + kf * 4;
            const uint32_t* qb = ql + kf * 4;
#pragma unroll
            for (int p = 0; p < 4; ++p) {
                const uint32_t bo = SW128B(
                    (uint32_t)((brow + p * 16) * 128 + (kf * 16 + bcol) * 2));
                uint32_t kh0, kh1, kh2, kh3, kl0, kl1, kl2, kl3;
                LDSM_X4(kh0, kh1, kh2, kh3, st + bo);
                LDSM_X4(kl0, kl1, kl2, kl3, st + AT_B + bo);
                float* c0 = s + (2 * p) * 4;
                float* c1 = s + (2 * p + 1) * 4;
                MMA16816(c0, qa[0], qa[1], qa[2], qa[3], kh0, kh1);
                MMA16816(c0, qa[0], qa[1], qa[2], qa[3], kl0, kl1);
                MMA16816(c0, qb[0], qb[1], qb[2], qb[3], kh0, kh1);
                MMA16816(c1, qa[0], qa[1], qa[2], qa[3], kh2, kh3);
                MMA16816(c1, qa[0], qa[1], qa[2], qa[3], kl2, kl3);
                MMA16816(c1, qb[0], qb[1], qb[2], qb[3], kh2, kh3);
            }
        }

        // ---- decay + online softmax
#pragma unroll
        for (int r = 0; r < 2; ++r) {
            const int iq = r0g + r * 8;
            float rmax = -INFINITY;
#pragma unroll
            for (int nt = 0; nt < 8; ++nt) {
#pragma unroll
                for (int e = 0; e < 2; ++e) {
                    const int j = kt * 64 + nt * 8 + jb0 + e;
                    int di = iq - j; di = di < 0 ? -di : di;
                    const float v = s[nt * 4 + r * 2 + e] * dec[di];
                    s[nt * 4 + r * 2 + e] = v;
                    rmax = fmaxf(rmax, v);
                }
            }
            rmax = fmaxf(rmax, __shfl_xor_sync(0xffffffffu, rmax, 1));
            rmax = fmaxf(rmax, __shfl_xor_sync(0xffffffffu, rmax, 2));
            const float mn = fmaxf(m[r], rmax);
            const float alpha = __expf(m[r] - mn);
            m[r] = mn;
            float rsum = 0.f;
#pragma unroll
            for (int nt = 0; nt < 8; ++nt) {
#pragma unroll
                for (int e = 0; e < 2; ++e) {
                    const float p = __expf(s[nt * 4 + r * 2 + e] - mn);
                    s[nt * 4 + r * 2 + e] = p;
                    rsum += p;
                }
            }
            rsum += __shfl_xor_sync(0xffffffffu, rsum, 1);
            rsum += __shfl_xor_sync(0xffffffffu, rsum, 2);
            l[r] = l[r] * alpha + rsum;
#pragma unroll
            for (int nt = 0; nt < 8; ++nt) {
                o[nt * 4 + r * 2]     *= alpha;
                o[nt * 4 + r * 2 + 1] *= alpha;
            }
        }

        // ---- pack P into A-frags (hi + residual lo)
        uint32_t ph[16], pl[16];
#pragma unroll
        for (int kf = 0; kf < 4; ++kf) {
#pragma unroll
            for (int q = 0; q < 4; ++q) {
                const int nt = 2 * kf + (q >> 1);
                const int base = nt * 4 + (q & 1) * 2;
                const float f0 = s[base], f1 = s[base + 1];
                const __half h0 = __float2half_rn(f0);
                const __half h1 = __float2half_rn(f1);
                __half2 hh = __halves2half2(h0, h1);
                ph[kf * 4 + q] = *reinterpret_cast<uint32_t*>(&hh);
                __half2 llv = __halves2half2(
                    __float2half_rn(f0 - __half2float(h0)),
                    __float2half_rn(f1 - __half2float(h1)));
                pl[kf * 4 + q] = *reinterpret_cast<uint32_t*>(&llv);
            }
        }

        // ---- O += P * V   (V via ldmatrix.trans)
#pragma unroll
        for (int tf = 0; tf < 4; ++tf) {
            const uint32_t* pa = ph + tf * 4;
            const uint32_t* pb = pl + tf * 4;
#pragma unroll
            for (int p = 0; p < 4; ++p) {
                const uint32_t bo = SW128B(
                    (uint32_t)((tf * 16 + trow) * 128 + (p * 16 + tcol) * 2));
                uint32_t vh0, vh1, vh2, vh3, vl0, vl1, vl2, vl3;
                LDSM_X4_T(vh0, vh1, vh2, vh3, st + 2 * AT_B + bo);
                LDSM_X4_T(vl0, vl1, vl2, vl3, st + 3 * AT_B + bo);
                float* c0 = o + (2 * p) * 4;
                float* c1 = o + (2 * p + 1) * 4;
                MMA16816(c0, pa[0], pa[1], pa[2], pa[3], vh0, vh1);
                MMA16816(c0, pa[0], pa[1], pa[2], pa[3], vl0, vl1);
                MMA16816(c0, pb[0], pb[1], pb[2], pb[3], vh0, vh1);
                MMA16816(c1, pa[0], pa[1], pa[2], pa[3], vh2, vh3);
                MMA16816(c1, pa[0], pa[1], pa[2], pa[3], vl2, vl3);
                MMA16816(c1, pb[0], pb[1], pb[2], pb[3], vh2, vh3);
            }
        }

        rd = rd == 2 ? 0 : rd + 1;
        wr = wr == 2 ? 0 : wr + 1;
    }

    // ---- epilogue: normalize, write hi/lo for the out-projection
    const float inv0 = 1.0f / l[0], inv1 = 1.0f / l[1];
#pragma unroll
    for (int r = 0; r < 2; ++r) {
        const float inv = r ? inv1 : inv0;
        const size_t rowoff =
            ((size_t)(b * PS + r0g + r * 8)) * PE + h * 64 + jb0;
#pragma unroll
        for (int nt = 0; nt < 8; ++nt) {
            const float v0 = o[nt * 4 + r * 2] * inv;
            const float v1 = o[nt * 4 + r * 2 + 1] * inv;
            const __half h0 = __float2half_rn(v0);
            const __half h1 = __float2half_rn(v1);
            *(__half2*)(ahi + rowoff + nt * 8) = __halves2half2(h0, h1);
            *(__half2*)(alo + rowoff + nt * 8) = __halves2half2(
                __float2half_rn(v0 - __half2float(h0)),
                __float2half_rn(v1 - __half2float(h1)));
        }
    }
}

// ---------------------------------------------------------------------------
extern "C" void kernel_launch(void* const* d_in, const int* in_sizes, int n_in,
                              void* d_out, int out_size)
{
    const float* x      = (const float*)d_in[0];
    const float* Wqkv_w = (const float*)d_in[1];
    const float* Wqkv_b = (const float*)d_in[2];
    const float* out_w  = (const float*)d_in[3];
    const float* out_b  = (const float*)d_in[4];
    const float* dd     = (const float*)d_in[5];
    float* outp = (float*)d_out;

    __half *qkvhi, *qkvlo, *xhi, *xlo, *whi, *wlo, *owhi, *owlo, *ahi, *alo;
    cudaGetSymbolAddress((void**)&qkvhi, g_qkvhi);
    cudaGetSymbolAddress((void**)&qkvlo, g_qkvlo);
    cudaGetSymbolAddress((void**)&xhi,  g_xhi);
    cudaGetSymbolAddress((void**)&xlo,  g_xlo);
    cudaGetSymbolAddress((void**)&whi,  g_whi);
    cudaGetSymbolAddress((void**)&wlo,  g_wlo);
    cudaGetSymbolAddress((void**)&owhi, g_owhi);
    cudaGetSymbolAddress((void**)&owlo, g_owlo);
    cudaGetSymbolAddress((void**)&ahi,  g_ahi);
    cudaGetSymbolAddress((void**)&alo,  g_alo);

    cudaFuncSetAttribute(gemm_tc<1>,
                         cudaFuncAttributeMaxDynamicSharedMemorySize, SMEM_GEMM);
    cudaFuncSetAttribute(gemm_tc<0>,
                         cudaFuncAttributeMaxDynamicSharedMemorySize, SMEM_GEMM);
    cudaFuncSetAttribute(attn_tc,
                         cudaFuncAttributeMaxDynamicSharedMemorySize, SMEM_ATTN);

    // 0) fp32 -> fp16 hi/lo splits of the input operands
    split_kernel<<<(PB * PS * PE / 4 + 255) / 256, 256>>>(x, xhi, xlo, PB * PS * PE / 4);
    split_kernel<<<(3 * PE * PE / 4 + 255) / 256, 256>>>(Wqkv_w, whi, wlo, 3 * PE * PE / 4);
    split_kernel<<<(PE * PE / 4 + 255) / 256, 256>>>(out_w, owhi, owlo, PE * PE / 4);

    // 1) QKV projection, epilogue writes hi/lo fp16 directly
    gemm_tc<1><<<dim3(3072 / 128, 4096 / 128), 256, SMEM_GEMM>>>(
        xhi, xlo, whi, wlo, Wqkv_b, nullptr, qkvhi, qkvlo, 3072, 1024);

    // 2) tensor-core flash attention with distance decay -> hi/lo
    attn_tc<<<dim3(PS / 128, PB * PH), 256, SMEM_ATTN>>>(
        qkvhi, qkvlo, ahi, alo, dd);

    // 3) output projection -> fp32 result
    gemm_tc<0><<<dim3(1024 / 128, 4096 / 128), 256, SMEM_GEMM>>>(
        ahi, alo, owhi, owlo, out_b, outp, nullptr, nullptr, 1024, 1024);
}